// round 1
// baseline (speedup 1.0000x reference)
#include <cuda_runtime.h>
#include <cuda_bf16.h>
#include <mma.h>

using namespace nvcuda;

// Problem dims (fixed)
#define BDIM 32
#define TDIM 4096
#define DDIM 512
#define MDIM (BDIM * TDIM)   // 131072

// GEMM tiling
#define BM 128
#define BN 64
#define BK 32
#define PAD 4                 // smem row pad (floats): stride 36 = 144B (16B multiple)

#define CHUNKS 8              // softmax time-chunks per batch

// ---------------- scratch (device globals; no allocation allowed) ----------------
__device__ float g_u[(long)MDIM * DDIM];   // tanh(h@W1^T + b1)
__device__ float g_s[(long)MDIM * DDIM];   // u@W2^T (logits)
__device__ float g_m[BDIM * CHUNKS * DDIM];
__device__ float g_z[BDIM * CHUNKS * DDIM];
__device__ float g_a[BDIM * CHUNKS * DDIM];

__device__ __forceinline__ float fast_tanh(float x) {
    // tanh(x) = 1 - 2/(exp(2x)+1); safe at +/-inf of exp
    float e = __expf(2.0f * x);
    return 1.0f - 2.0f / (e + 1.0f);
}

// ---------------- tf32 WMMA GEMM: C[M,N] = op(A[M,K] @ W[N,K]^T) ----------------
// A row-major [M, 512], W row-major [N=512, K=512].
// TANH: C = tanh(AB + bias[col]) else C = AB.
template <bool TANH>
__global__ __launch_bounds__(256)
void gemm_tf32_kernel(const float* __restrict__ A,
                      const float* __restrict__ W,
                      const float* __restrict__ bias,
                      float* __restrict__ C) {
    const int K = DDIM, N = DDIM;

    __shared__ float sm[BM * BN];  // 8192 floats; unioned: As+Bs (6912) then C tile
    float (*As)[BK + PAD] = (float(*)[BK + PAD])sm;                    // 128 x 36
    float (*Bs)[BK + PAD] = (float(*)[BK + PAD])(sm + BM * (BK + PAD)); // 64 x 36

    const int tid = threadIdx.x;
    const int warp_id = tid >> 5;
    const int warp_row = warp_id & 3;   // 4 warps along M  (4*32 = 128)
    const int warp_col = warp_id >> 2;  // 2 warps along N  (2*32 = 64)

    const int block_row = blockIdx.y * BM;
    const int block_col = blockIdx.x * BN;

    wmma::fragment<wmma::accumulator, 16, 16, 8, float> c[2][2];
#pragma unroll
    for (int i = 0; i < 2; i++)
#pragma unroll
        for (int j = 0; j < 2; j++) wmma::fill_fragment(c[i][j], 0.0f);

    for (int kt = 0; kt < K; kt += BK) {
        // ---- load A tile: BM x BK (1024 float4, 4 per thread) ----
#pragma unroll
        for (int it = 0; it < (BM * BK / 4) / 256; it++) {
            int i = tid + it * 256;
            int r = i / (BK / 4);
            int c4 = i % (BK / 4);
            float4 v = *(const float4*)(A + (long)(block_row + r) * K + kt + c4 * 4);
            *(float4*)(&As[r][c4 * 4]) = v;
        }
        // ---- load B tile: BN x BK (512 float4, 2 per thread) ----
#pragma unroll
        for (int it = 0; it < (BN * BK / 4) / 256; it++) {
            int i = tid + it * 256;
            int r = i / (BK / 4);
            int c4 = i % (BK / 4);
            float4 v = *(const float4*)(W + (long)(block_col + r) * K + kt + c4 * 4);
            *(float4*)(&Bs[r][c4 * 4]) = v;
        }
        __syncthreads();

#pragma unroll
        for (int kk = 0; kk < BK; kk += 8) {
            wmma::fragment<wmma::matrix_a, 16, 16, 8, wmma::precision::tf32, wmma::row_major> a[2];
            wmma::fragment<wmma::matrix_b, 16, 16, 8, wmma::precision::tf32, wmma::col_major> b[2];
#pragma unroll
            for (int i = 0; i < 2; i++) {
                wmma::load_matrix_sync(a[i], &As[warp_row * 32 + i * 16][kk], BK + PAD);
#pragma unroll
                for (int t = 0; t < a[i].num_elements; t++)
                    a[i].x[t] = wmma::__float_to_tf32(a[i].x[t]);
            }
#pragma unroll
            for (int j = 0; j < 2; j++) {
                wmma::load_matrix_sync(b[j], &Bs[warp_col * 32 + j * 16][kk], BK + PAD);
#pragma unroll
                for (int t = 0; t < b[j].num_elements; t++)
                    b[j].x[t] = wmma::__float_to_tf32(b[j].x[t]);
            }
#pragma unroll
            for (int i = 0; i < 2; i++)
#pragma unroll
                for (int j = 0; j < 2; j++)
                    wmma::mma_sync(c[i][j], a[i], b[j], c[i][j]);
        }
        __syncthreads();
    }

    // ---- epilogue via smem C tile (reuse union) ----
    float* Cs = sm;  // 128 x 64 row-major, ldm=64
#pragma unroll
    for (int i = 0; i < 2; i++)
#pragma unroll
        for (int j = 0; j < 2; j++)
            wmma::store_matrix_sync(&Cs[(warp_row * 32 + i * 16) * BN + warp_col * 32 + j * 16],
                                    c[i][j], BN, wmma::mem_row_major);
    __syncthreads();

#pragma unroll
    for (int it = 0; it < (BM * BN / 4) / 256; it++) {   // 8 iters
        int i = tid + it * 256;
        int r = i / (BN / 4);
        int c4 = i % (BN / 4);
        float4 v = *(float4*)&Cs[r * BN + c4 * 4];
        if (TANH) {
            int col = block_col + c4 * 4;
            v.x = fast_tanh(v.x + bias[col + 0]);
            v.y = fast_tanh(v.y + bias[col + 1]);
            v.z = fast_tanh(v.z + bias[col + 2]);
            v.w = fast_tanh(v.w + bias[col + 3]);
        }
        *(float4*)(C + (long)(block_row + r) * N + block_col + c4 * 4) = v;
    }
}

// ---------------- chunked online softmax over T + weighted sum of h ----------------
// grid: (D/128, CHUNKS, B), block: 128 threads. Each thread scans one (b,d) column
// over its T-chunk of s (logits) and h, producing partial (m, Z, acc).
__global__ __launch_bounds__(128)
void scan_kernel(const float* __restrict__ s, const float* __restrict__ h) {
    const int d = blockIdx.x * 128 + threadIdx.x;
    const int c = blockIdx.y;
    const int b = blockIdx.z;
    const int TC = TDIM / CHUNKS;  // 512

    int base = ((b * TDIM) + c * TC) * DDIM + d;

    float m = -1e30f, Z = 0.0f, acc = 0.0f;
#pragma unroll 4
    for (int t = 0; t < TC; t++) {
        float x = s[base + t * DDIM];
        float hv = h[base + t * DDIM];
        float nm = fmaxf(m, x);
        float corr = __expf(m - nm);
        float p = __expf(x - nm);
        Z = Z * corr + p;
        acc = acc * corr + hv * p;
        m = nm;
    }
    int idx = (b * CHUNKS + c) * DDIM + d;
    g_m[idx] = m;
    g_z[idx] = Z;
    g_a[idx] = acc;
}

// Merge chunk partials per batch, then sum batch contributions -> out[512]
__global__ __launch_bounds__(128)
void merge_kernel(float* __restrict__ out) {
    const int d = blockIdx.x * 128 + threadIdx.x;
    float total = 0.0f;
    for (int b = 0; b < BDIM; b++) {
        float M = -1e30f;
#pragma unroll
        for (int c = 0; c < CHUNKS; c++)
            M = fmaxf(M, g_m[(b * CHUNKS + c) * DDIM + d]);
        float Z = 0.0f, Acc = 0.0f;
#pragma unroll
        for (int c = 0; c < CHUNKS; c++) {
            int idx = (b * CHUNKS + c) * DDIM + d;
            float e = __expf(g_m[idx] - M);
            Z += g_z[idx] * e;
            Acc += g_a[idx] * e;
        }
        total += Acc / Z;
    }
    out[d] = total;
}

// ---------------- host launcher ----------------
extern "C" void kernel_launch(void* const* d_in, const int* in_sizes, int n_in,
                              void* d_out, int out_size) {
    const float* h  = (const float*)d_in[0];
    const float* W1 = (const float*)d_in[1];
    const float* b1 = (const float*)d_in[2];
    const float* W2 = (const float*)d_in[3];
    float* out = (float*)d_out;

    float *u_ptr, *s_ptr;
    cudaGetSymbolAddress((void**)&u_ptr, g_u);
    cudaGetSymbolAddress((void**)&s_ptr, g_s);

    dim3 ggrid(DDIM / BN, MDIM / BM);   // (8, 1024)

    // u = tanh(h @ W1^T + b1)
    gemm_tf32_kernel<true><<<ggrid, 256>>>(h, W1, b1, u_ptr);
    // s = u @ W2^T
    gemm_tf32_kernel<false><<<ggrid, 256>>>(u_ptr, W2, nullptr, s_ptr);
    // online softmax over T (chunked) + weighted accumulation of h
    dim3 sgrid(DDIM / 128, CHUNKS, BDIM);
    scan_kernel<<<sgrid, 128>>>(s_ptr, h);
    // merge partials -> out[512]
    merge_kernel<<<DDIM / 128, 128>>>(out);
}

// round 3
// speedup vs baseline: 2.1737x; 2.1737x over previous
#include <cuda_runtime.h>
#include <cstdint>

// ---------------- problem dims ----------------
#define BDIM 32
#define TDIM 4096
#define DDIM 512
#define MDIM (BDIM * TDIM)          // 131072

// ---------------- GEMM tiling ----------------
#define TILE_M 128
#define TILE_N 128
#define BK 16                        // k floats per chunk
#define NCHUNK (DDIM / BK)           // 32
#define STAGES 4
#define ROWF 20                      // padded row stride in floats (80B: 5*16B -> conflict-free)
#define A_FLOATS (TILE_M * ROWF)     // 2560
#define B_FLOATS (TILE_N * ROWF)     // 2560
#define STAGE_FLOATS (A_FLOATS + B_FLOATS)
#define SMEM_BYTES (STAGES * STAGE_FLOATS * 4)   // 81920

#define CHUNKS 16                    // softmax time-chunks per batch

// ---------------- scratch ----------------
__device__ float g_u[(size_t)MDIM * DDIM];
__device__ float g_s[(size_t)MDIM * DDIM];
__device__ float g_m[BDIM * CHUNKS * DDIM];
__device__ float g_z[BDIM * CHUNKS * DDIM];
__device__ float g_a[BDIM * CHUNKS * DDIM];
__device__ float g_r[BDIM * DDIM];

// ---------------- helpers ----------------
__device__ __forceinline__ uint32_t smem_u32(const void* p) {
    uint32_t a;
    asm("{ .reg .u64 t; cvta.to.shared.u64 t, %1; cvt.u32.u64 %0, t; }" : "=r"(a) : "l"(p));
    return a;
}
__device__ __forceinline__ void cp16(uint32_t dst, const void* src) {
    asm volatile("cp.async.cg.shared.global [%0], [%1], 16;" :: "r"(dst), "l"(src));
}
__device__ __forceinline__ void ldsm4(uint32_t* r, uint32_t addr) {
    asm volatile("ldmatrix.sync.aligned.m8n8.x4.shared.b16 {%0,%1,%2,%3}, [%4];"
                 : "=r"(r[0]), "=r"(r[1]), "=r"(r[2]), "=r"(r[3]) : "r"(addr));
}
__device__ __forceinline__ uint32_t to_tf32(uint32_t x) {
    uint32_t y;
    asm("cvt.rna.tf32.f32 %0, %1;" : "=r"(y) : "f"(__uint_as_float(x)));
    return y;
}
__device__ __forceinline__ void mma8(float* c, const uint32_t* a, const uint32_t* b) {
    asm volatile(
        "mma.sync.aligned.m16n8k8.row.col.f32.tf32.tf32.f32 "
        "{%0,%1,%2,%3}, {%4,%5,%6,%7}, {%8,%9}, {%0,%1,%2,%3};"
        : "+f"(c[0]), "+f"(c[1]), "+f"(c[2]), "+f"(c[3])
        : "r"(a[0]), "r"(a[1]), "r"(a[2]), "r"(a[3]), "r"(b[0]), "r"(b[1]));
}
__device__ __forceinline__ float fast_tanh(float x) {
    float e = __expf(2.0f * x);
    return 1.0f - 2.0f / (e + 1.0f);
}

// ---------------- stage loader: A 128x16f, W 128x16f, padded rows ----------------
__device__ __forceinline__ void load_stage(const float* __restrict__ A,
                                           const float* __restrict__ W,
                                           int m0, int n0, int kc,
                                           uint32_t stA, uint32_t stB, int tid) {
#pragma unroll
    for (int it = 0; it < 2; it++) {             // 512 chunks of 16B for A
        int idx = tid + it * 256;
        int r = idx >> 2, c = idx & 3;
        cp16(stA + r * 80 + c * 16, A + (size_t)(m0 + r) * DDIM + kc * BK + c * 4);
    }
#pragma unroll
    for (int it = 0; it < 2; it++) {             // 512 chunks for W tile
        int idx = tid + it * 256;
        int r = idx >> 2, c = idx & 3;
        cp16(stB + r * 80 + c * 16, W + (size_t)(n0 + r) * DDIM + kc * BK + c * 4);
    }
}

// ---------------- tf32 mma.sync GEMM: C[M,N] = op(A[M,K] @ W[N,K]^T) ----------------
template <bool TANH>
__global__ void __launch_bounds__(256, 2)
gemm_mma(const float* __restrict__ A, const float* __restrict__ W,
         const float* __restrict__ bias, float* __restrict__ C) {
    extern __shared__ float sm[];
    const int tid = threadIdx.x;
    const int lane = tid & 31;
    const int wid = tid >> 5;

    const int m0 = blockIdx.y * TILE_M;
    const int n0 = blockIdx.x * TILE_N;
    const int wm = (wid >> 2) * 64;              // warp row offset (2 warps along M)
    const int wn = (wid & 3) * 32;               // warp col offset (4 warps along N)

    float acc[4][4][4];                          // [m-frag][n-frag][c0..c3]
#pragma unroll
    for (int i = 0; i < 4; i++)
#pragma unroll
        for (int j = 0; j < 4; j++)
#pragma unroll
            for (int k = 0; k < 4; k++) acc[i][j][k] = 0.0f;

    const uint32_t s_base = smem_u32(sm);

    // per-lane ldmatrix offsets (bytes within a stage)
    //   A tiles: lanes 0-7 rows0-7/klo, 8-15 rows8-15/klo, 16-23 rows0-7/khi, 24-31 rows8-15/khi
    const uint32_t a_off = (uint32_t)(wm + ((lane >> 3) & 1) * 8 + (lane & 7)) * 80
                           + (uint32_t)(lane >> 4) * 16;
    //   B tiles: lanes 0-7 n0-7/klo, 8-15 n0-7/khi, 16-23 n8-15/klo, 24-31 n8-15/khi
    const uint32_t b_off = (uint32_t)(wn + (lane >> 4) * 8 + (lane & 7)) * 80
                           + (uint32_t)((lane >> 3) & 1) * 16;

    // ---- prologue: 3 stages in flight ----
#pragma unroll
    for (int s = 0; s < STAGES - 1; s++) {
        load_stage(A, W, m0, n0, s,
                   s_base + s * STAGE_FLOATS * 4,
                   s_base + s * STAGE_FLOATS * 4 + A_FLOATS * 4, tid);
        asm volatile("cp.async.commit_group;" ::: "memory");
    }

    // ---- main loop ----
    for (int i = 0; i < NCHUNK; i++) {
        asm volatile("cp.async.wait_group %0;" :: "n"(STAGES - 2));
        __syncthreads();

        const int j = i + STAGES - 1;
        if (j < NCHUNK) {
            load_stage(A, W, m0, n0, j,
                       s_base + (j & 3) * STAGE_FLOATS * 4,
                       s_base + (j & 3) * STAGE_FLOATS * 4 + A_FLOATS * 4, tid);
        }
        asm volatile("cp.async.commit_group;" ::: "memory");

        const uint32_t stA = s_base + (i & 3) * STAGE_FLOATS * 4;
        const uint32_t stB = stA + A_FLOATS * 4;

#pragma unroll
        for (int kk = 0; kk < 2; kk++) {         // two k8 steps per BK=16
            uint32_t br[2][4];
#pragma unroll
            for (int g = 0; g < 2; g++) {        // n-cols g*16..g*16+15
                ldsm4(br[g], stB + b_off + g * 16 * 80 + kk * 32);
#pragma unroll
                for (int t = 0; t < 4; t++) br[g][t] = to_tf32(br[g][t]);
            }
            uint32_t ar[4][4];
#pragma unroll
            for (int f = 0; f < 4; f++) {        // m-rows f*16..f*16+15
                ldsm4(ar[f], stA + a_off + f * 16 * 80 + kk * 32);
#pragma unroll
                for (int t = 0; t < 4; t++) ar[f][t] = to_tf32(ar[f][t]);
            }
#pragma unroll
            for (int fm = 0; fm < 4; fm++) {
#pragma unroll
                for (int fn = 0; fn < 4; fn++) {
                    const uint32_t b2[2] = { br[fn >> 1][(fn & 1) * 2],
                                             br[fn >> 1][(fn & 1) * 2 + 1] };
                    mma8(acc[fm][fn], ar[fm], b2);
                }
            }
        }
    }

    // ---- epilogue: direct coalesced-ish v2 stores ----
    const int g = lane >> 2;                     // row within 8-row group
    const int tg = lane & 3;                     // col pair index
#pragma unroll
    for (int fm = 0; fm < 4; fm++) {
        const int row = m0 + wm + fm * 16 + g;
#pragma unroll
        for (int fn = 0; fn < 4; fn++) {
            const int col = n0 + wn + fn * 8 + tg * 2;
            float v0 = acc[fm][fn][0], v1 = acc[fm][fn][1];
            float v2 = acc[fm][fn][2], v3 = acc[fm][fn][3];
            if (TANH) {
                const float2 bb = *(const float2*)(bias + col);
                v0 = fast_tanh(v0 + bb.x);
                v1 = fast_tanh(v1 + bb.y);
                v2 = fast_tanh(v2 + bb.x);
                v3 = fast_tanh(v3 + bb.y);
            }
            *(float2*)(C + (size_t)row * DDIM + col) = make_float2(v0, v1);
            *(float2*)(C + (size_t)(row + 8) * DDIM + col) = make_float2(v2, v3);
        }
    }
}

// ---------------- chunked online softmax over T + weighted sum of h ----------------
__global__ void __launch_bounds__(128)
scan_kernel(const float* __restrict__ s, const float* __restrict__ h) {
    const int d = blockIdx.x * 128 + threadIdx.x;
    const int c = blockIdx.y;
    const int b = blockIdx.z;
    const int TC = TDIM / CHUNKS;                // 256

    size_t base = ((size_t)(b * TDIM) + (size_t)c * TC) * DDIM + d;

    float m = -1e30f, Z = 0.0f, acc = 0.0f;
#pragma unroll 4
    for (int t = 0; t < TC; t++) {
        float x = s[base + (size_t)t * DDIM];
        float hv = h[base + (size_t)t * DDIM];
        float nm = fmaxf(m, x);
        float corr = __expf(m - nm);
        float p = __expf(x - nm);
        Z = Z * corr + p;
        acc = acc * corr + hv * p;
        m = nm;
    }
    int idx = (b * CHUNKS + c) * DDIM + d;
    g_m[idx] = m;
    g_z[idx] = Z;
    g_a[idx] = acc;
}

// merge1: per (b, d) combine chunk partials -> ratio
__global__ void __launch_bounds__(128)
merge1_kernel() {
    const int d = blockIdx.x * 128 + threadIdx.x;
    const int b = blockIdx.y;
    float M = -1e30f;
#pragma unroll
    for (int c = 0; c < CHUNKS; c++)
        M = fmaxf(M, g_m[(b * CHUNKS + c) * DDIM + d]);
    float Z = 0.0f, Acc = 0.0f;
#pragma unroll
    for (int c = 0; c < CHUNKS; c++) {
        int idx = (b * CHUNKS + c) * DDIM + d;
        float e = __expf(g_m[idx] - M);
        Z += g_z[idx] * e;
        Acc += g_a[idx] * e;
    }
    g_r[b * DDIM + d] = Acc / Z;
}

// merge2: sum over batches -> out[512]
__global__ void __launch_bounds__(128)
merge2_kernel(float* __restrict__ out) {
    const int d = blockIdx.x * 128 + threadIdx.x;
    float total = 0.0f;
#pragma unroll
    for (int b = 0; b < BDIM; b++) total += g_r[b * DDIM + d];
    out[d] = total;
}

// ---------------- host launcher ----------------
extern "C" void kernel_launch(void* const* d_in, const int* in_sizes, int n_in,
                              void* d_out, int out_size) {
    const float* h  = (const float*)d_in[0];
    const float* W1 = (const float*)d_in[1];
    const float* b1 = (const float*)d_in[2];
    const float* W2 = (const float*)d_in[3];
    float* out = (float*)d_out;

    float *u_ptr, *s_ptr;
    cudaGetSymbolAddress((void**)&u_ptr, g_u);
    cudaGetSymbolAddress((void**)&s_ptr, g_s);

    cudaFuncSetAttribute(gemm_mma<true>,  cudaFuncAttributeMaxDynamicSharedMemorySize, SMEM_BYTES);
    cudaFuncSetAttribute(gemm_mma<false>, cudaFuncAttributeMaxDynamicSharedMemorySize, SMEM_BYTES);

    dim3 ggrid(DDIM / TILE_N, MDIM / TILE_M);    // (4, 1024) — x fastest: n-CTAs share A tile in L2

    gemm_mma<true><<<ggrid, 256, SMEM_BYTES>>>(h, W1, b1, u_ptr);        // u = tanh(h@W1^T + b1)
    gemm_mma<false><<<ggrid, 256, SMEM_BYTES>>>(u_ptr, W2, nullptr, s_ptr);  // s = u@W2^T

    dim3 sgrid(DDIM / 128, CHUNKS, BDIM);
    scan_kernel<<<sgrid, 128>>>(s_ptr, h);

    dim3 m1grid(DDIM / 128, BDIM);
    merge1_kernel<<<m1grid, 128>>>();
    merge2_kernel<<<DDIM / 128, 128>>>(out);
}